// round 3
// baseline (speedup 1.0000x reference)
#include <cuda_runtime.h>

#define NROWS 100000
#define DIMX  592
#define NINV  128
#define NEQ   464
#define NCH   240
#define NSEG  112
#define RT    8          // rows per CTA
#define NTHR  128

// ---- Blackwell packed f32x2 helpers (FFMA2) ----
static __device__ __forceinline__ unsigned long long ffma2(unsigned long long a,
                                                           unsigned long long b,
                                                           unsigned long long c) {
    unsigned long long d;
    asm("fma.rn.f32x2 %0, %1, %2, %3;" : "=l"(d) : "l"(a), "l"(b), "l"(c));
    return d;
}
static __device__ __forceinline__ unsigned long long pack2(float x, float y) {
    unsigned long long r;
    asm("mov.b64 %0, {%1, %2};" : "=l"(r)
        : "r"(__float_as_uint(x)), "r"(__float_as_uint(y)));
    return r;
}
static __device__ __forceinline__ void unpack2(unsigned long long v, float& x, float& y) {
    unsigned a, b;
    asm("mov.b64 {%0, %1}, %2;" : "=r"(a), "=r"(b) : "l"(v));
    x = __uint_as_float(a);
    y = __uint_as_float(b);
}

// Block-wide LayerNorm stats for RT rows: each thread holds one channel's value
// per row; returns per-row mean and rstd to every thread.
static __device__ __forceinline__ void block_ln_stats(const float* hv,
                                                      float (*s_red)[RT][2],
                                                      float* mu, float* rs) {
    int lane = threadIdx.x & 31;
    int w    = threadIdx.x >> 5;
#pragma unroll
    for (int r = 0; r < RT; r++) {
        float v = hv[r];
        float s = v, q = v * v;
#pragma unroll
        for (int o = 16; o; o >>= 1) {
            s += __shfl_xor_sync(0xffffffffu, s, o);
            q += __shfl_xor_sync(0xffffffffu, q, o);
        }
        if (lane == 0) { s_red[w][r][0] = s; s_red[w][r][1] = q; }
    }
    __syncthreads();
#pragma unroll
    for (int r = 0; r < RT; r++) {
        float s = s_red[0][r][0] + s_red[1][r][0] + s_red[2][r][0] + s_red[3][r][0];
        float q = s_red[0][r][1] + s_red[1][r][1] + s_red[2][r][1] + s_red[3][r][1];
        float m   = s * (1.0f / NINV);
        float var = q * (1.0f / NINV) - m * m;
        mu[r] = m;
        rs[r] = rsqrtf(var + 1e-5f);
    }
    __syncthreads();   // protect s_red reuse AND act as the s_h overwrite barrier
}

__global__ void __launch_bounds__(NTHR) evmlp_kernel(
    const float* __restrict__ ten,
    const float* __restrict__ w1, const float* __restrict__ g1, const float* __restrict__ be1,
    const float* __restrict__ w2, const float* __restrict__ b2,
    const float* __restrict__ g2, const float* __restrict__ be2,
    const float* __restrict__ w3, const float* __restrict__ b3,
    float* __restrict__ out)
{
    __shared__ __align__(16) float s_ten[RT * DIMX];     // 18944 B
    __shared__ __align__(16) float s_x1[NCH * RT];       // 7680 B   layout [k][r]
    __shared__ __align__(16) float s_h[NINV * RT];       // 4096 B   layout [k][r]
    __shared__ float s_rdiv[RT * NSEG];                  // 3584 B
    __shared__ float s_red[4][RT][2];                    // 256 B

    const int tid = threadIdx.x;
    const long long row0 = (long long)blockIdx.x * RT;

    // ---------- Phase A: load 8 rows, equivariant head ----------
    {
        const float4* g4 = reinterpret_cast<const float4*>(ten + row0 * DIMX);
        float4* s4 = reinterpret_cast<float4*>(s_ten);
        for (int i = tid; i < (RT * DIMX) / 4; i += NTHR) s4[i] = g4[i];
    }
    __syncthreads();

    // x10 copy into x1 (layout [k][r])
    for (int j = tid; j < RT * NINV; j += NTHR) {
        int r = j >> 7;
        int c = j & 127;
        s_x1[c * RT + r] = s_ten[r * DIMX + c];
    }
    // per-segment sumsq -> x11 + reciprocal divisor
    if (tid < NSEG) {
        int t = tid, base, len;
        if (t < 64)      { base = 3 * t;              len = 3; }
        else if (t < 96) { base = 192 + 5 * (t - 64); len = 5; }
        else             { base = 352 + 7 * (t - 96); len = 7; }
#pragma unroll
        for (int r = 0; r < RT; r++) {
            const float* e = &s_ten[r * DIMX + NINV + base];
            float ss = 1.0f;
            for (int j = 0; j < len; j++) ss += e[j] * e[j];
            float dv = sqrtf(ss);
            s_x1[(NINV + t) * RT + r] = dv - 1.0f;
            s_rdiv[r * NSEG + t] = 1.0f / dv;
        }
    }
    __syncthreads();

    // x2 = eq * rdiv[seg]  -> out columns [128, 592)
#pragma unroll 1
    for (int r = 0; r < RT; r++) {
        float*       orow = out + (row0 + r) * DIMX + NINV;
        const float* erow = &s_ten[r * DIMX + NINV];
        const float* rd   = &s_rdiv[r * NSEG];
        for (unsigned i = tid; i < NEQ; i += NTHR) {
            unsigned s;
            if (i < 192u)      s = i / 3u;
            else if (i < 352u) s = 64u + (i - 192u) / 5u;
            else               s = 96u + (i - 352u) / 7u;
            orow[i] = erow[i] * rd[s];
        }
    }

    // ---------- Phase B: MLP, thread tid owns channel c ----------
    const int c = tid;
    float hv[8], mu[RT], rs[RT];

    // GEMM1: h = x1 @ w1   (K = 240)
    {
        unsigned long long acc0 = 0ull, acc1 = 0ull, acc2 = 0ull, acc3 = 0ull;
        const float* wc = w1 + c;
#pragma unroll 4
        for (int k = 0; k < NCH; k++) {
            float w = __ldg(wc + k * NINV);
            unsigned long long wp = pack2(w, w);
            const ulonglong2* xk = reinterpret_cast<const ulonglong2*>(&s_x1[k * RT]);
            ulonglong2 a = xk[0], b = xk[1];
            acc0 = ffma2(a.x, wp, acc0);
            acc1 = ffma2(a.y, wp, acc1);
            acc2 = ffma2(b.x, wp, acc2);
            acc3 = ffma2(b.y, wp, acc3);
        }
        unpack2(acc0, hv[0], hv[1]);
        unpack2(acc1, hv[2], hv[3]);
        unpack2(acc2, hv[4], hv[5]);
        unpack2(acc3, hv[6], hv[7]);
    }

    // LN1
    block_ln_stats(hv, s_red, mu, rs);
    {
        float g = g1[c], bb = be1[c];
#pragma unroll
        for (int r = 0; r < RT; r++) s_h[c * RT + r] = (hv[r] - mu[r]) * rs[r] * g + bb;
    }
    __syncthreads();

    // GEMM2: h @ w2 + b2   (K = 128)
    {
        float bc = b2[c];
        unsigned long long acc0 = pack2(bc, bc), acc1 = acc0, acc2 = acc0, acc3 = acc0;
        const float* wc = w2 + c;
#pragma unroll 4
        for (int k = 0; k < NINV; k++) {
            float w = __ldg(wc + k * NINV);
            unsigned long long wp = pack2(w, w);
            const ulonglong2* xk = reinterpret_cast<const ulonglong2*>(&s_h[k * RT]);
            ulonglong2 a = xk[0], b = xk[1];
            acc0 = ffma2(a.x, wp, acc0);
            acc1 = ffma2(a.y, wp, acc1);
            acc2 = ffma2(b.x, wp, acc2);
            acc3 = ffma2(b.y, wp, acc3);
        }
        unpack2(acc0, hv[0], hv[1]);
        unpack2(acc1, hv[2], hv[3]);
        unpack2(acc2, hv[4], hv[5]);
        unpack2(acc3, hv[6], hv[7]);
    }

    // SiLU
#pragma unroll
    for (int r = 0; r < RT; r++) {
        float v = hv[r];
        hv[r] = v / (1.0f + expf(-v));
    }

    // LN2 (the leading sync inside also guards s_h overwrite after GEMM2 reads)
    block_ln_stats(hv, s_red, mu, rs);
    {
        float g = g2[c], bb = be2[c];
#pragma unroll
        for (int r = 0; r < RT; r++) s_h[c * RT + r] = (hv[r] - mu[r]) * rs[r] * g + bb;
    }
    __syncthreads();

    // GEMM3: h @ w3 + b3   (K = 128) -> out columns [0,128)
    {
        float bc = b3[c];
        unsigned long long acc0 = pack2(bc, bc), acc1 = acc0, acc2 = acc0, acc3 = acc0;
        const float* wc = w3 + c;
#pragma unroll 4
        for (int k = 0; k < NINV; k++) {
            float w = __ldg(wc + k * NINV);
            unsigned long long wp = pack2(w, w);
            const ulonglong2* xk = reinterpret_cast<const ulonglong2*>(&s_h[k * RT]);
            ulonglong2 a = xk[0], b = xk[1];
            acc0 = ffma2(a.x, wp, acc0);
            acc1 = ffma2(a.y, wp, acc1);
            acc2 = ffma2(b.x, wp, acc2);
            acc3 = ffma2(b.y, wp, acc3);
        }
        unpack2(acc0, hv[0], hv[1]);
        unpack2(acc1, hv[2], hv[3]);
        unpack2(acc2, hv[4], hv[5]);
        unpack2(acc3, hv[6], hv[7]);
    }
#pragma unroll
    for (int r = 0; r < RT; r++) out[(row0 + r) * DIMX + c] = hv[r];
}

extern "C" void kernel_launch(void* const* d_in, const int* in_sizes, int n_in,
                              void* d_out, int out_size) {
    const float* ten = (const float*)d_in[0];
    // d_in[1] = rep_layout (int64) — layout is compile-time constant, unused
    const float* w1  = (const float*)d_in[2];
    const float* g1  = (const float*)d_in[3];
    const float* be1 = (const float*)d_in[4];
    const float* w2  = (const float*)d_in[5];
    const float* b2  = (const float*)d_in[6];
    const float* g2  = (const float*)d_in[7];
    const float* be2 = (const float*)d_in[8];
    const float* w3  = (const float*)d_in[9];
    const float* b3  = (const float*)d_in[10];

    evmlp_kernel<<<NROWS / RT, NTHR>>>(ten, w1, g1, be1, w2, b2, g2, be2, w3, b3,
                                       (float*)d_out);
}

// round 4
// speedup vs baseline: 1.2056x; 1.2056x over previous
#include <cuda_runtime.h>

#define NROWS 100000
#define DIMX  592
#define NINV  128
#define NEQ   464
#define NCH   240
#define NSEG  112
#define RTW   8        // rows per warp
#define RTC   32       // rows per CTA (4 warps)
#define NTHR  128
#define HSTR  12       // padded row stride (floats) of per-warp h buffer

// shared memory layout (floats)
#define OFF_TEN  0                    // [8*592]            phase A staging
#define OFF_X1   (RTW * DIMX)         // [240*32]           x1, layout [k][row]
#define OFF_H    (OFF_X1 + NCH * RTC) // [4][128*HSTR]      per-warp h, aliased by s_rdiv in phase A
#define SMEM_FLOATS (OFF_H + 4 * NINV * HSTR)

// ---- Blackwell packed f32x2 helpers ----
static __device__ __forceinline__ unsigned long long ffma2(unsigned long long a,
                                                           unsigned long long b,
                                                           unsigned long long c) {
    unsigned long long d;
    asm("fma.rn.f32x2 %0, %1, %2, %3;" : "=l"(d) : "l"(a), "l"(b), "l"(c));
    return d;
}
static __device__ __forceinline__ unsigned long long pack2(float x, float y) {
    unsigned long long r;
    asm("mov.b64 %0, {%1, %2};" : "=l"(r)
        : "r"(__float_as_uint(x)), "r"(__float_as_uint(y)));
    return r;
}
static __device__ __forceinline__ void unpack2(unsigned long long v, float& x, float& y) {
    unsigned a, b;
    asm("mov.b64 {%0, %1}, %2;" : "=r"(a), "=r"(b) : "l"(v));
    x = __uint_as_float(a);
    y = __uint_as_float(b);
}

// Warp-tile GEMM: 8 rows x 4 channels per thread.
// x is broadcast from shared ([k][row] layout, row stride XSTR floats, base
// already offset to this warp's 8 rows); W is (K, 128) row-major in gmem.
template<int K, int XSTR>
static __device__ __forceinline__ void warp_gemm(const float* __restrict__ W, int c0,
                                                 const float* xb, float4 bias,
                                                 float hv[4][8]) {
    unsigned long long acc[4][4];
    {
        float bb[4] = {bias.x, bias.y, bias.z, bias.w};
#pragma unroll
        for (int j = 0; j < 4; j++) {
            unsigned long long b = pack2(bb[j], bb[j]);
            acc[j][0] = b; acc[j][1] = b; acc[j][2] = b; acc[j][3] = b;
        }
    }
#pragma unroll 2
    for (int k = 0; k < K; k++) {
        float4 wv = __ldg(reinterpret_cast<const float4*>(W + k * NINV + c0));
        unsigned long long wp0 = pack2(wv.x, wv.x);
        unsigned long long wp1 = pack2(wv.y, wv.y);
        unsigned long long wp2 = pack2(wv.z, wv.z);
        unsigned long long wp3 = pack2(wv.w, wv.w);
        ulonglong2 xa = *reinterpret_cast<const ulonglong2*>(xb + k * XSTR);
        ulonglong2 xc = *reinterpret_cast<const ulonglong2*>(xb + k * XSTR + 4);
        acc[0][0] = ffma2(xa.x, wp0, acc[0][0]);
        acc[0][1] = ffma2(xa.y, wp0, acc[0][1]);
        acc[0][2] = ffma2(xc.x, wp0, acc[0][2]);
        acc[0][3] = ffma2(xc.y, wp0, acc[0][3]);
        acc[1][0] = ffma2(xa.x, wp1, acc[1][0]);
        acc[1][1] = ffma2(xa.y, wp1, acc[1][1]);
        acc[1][2] = ffma2(xc.x, wp1, acc[1][2]);
        acc[1][3] = ffma2(xc.y, wp1, acc[1][3]);
        acc[2][0] = ffma2(xa.x, wp2, acc[2][0]);
        acc[2][1] = ffma2(xa.y, wp2, acc[2][1]);
        acc[2][2] = ffma2(xc.x, wp2, acc[2][2]);
        acc[2][3] = ffma2(xc.y, wp2, acc[2][3]);
        acc[3][0] = ffma2(xa.x, wp3, acc[3][0]);
        acc[3][1] = ffma2(xa.y, wp3, acc[3][1]);
        acc[3][2] = ffma2(xc.x, wp3, acc[3][2]);
        acc[3][3] = ffma2(xc.y, wp3, acc[3][3]);
    }
#pragma unroll
    for (int j = 0; j < 4; j++) {
        unpack2(acc[j][0], hv[j][0], hv[j][1]);
        unpack2(acc[j][1], hv[j][2], hv[j][3]);
        unpack2(acc[j][2], hv[j][4], hv[j][5]);
        unpack2(acc[j][3], hv[j][6], hv[j][7]);
    }
}

// Warp-local LayerNorm stats: thread holds 4 channels x 8 rows; reduce 128
// channels per row across the warp by shuffle.
static __device__ __forceinline__ void ln_warp(const float hv[4][8], float* mu, float* rs) {
#pragma unroll
    for (int r = 0; r < RTW; r++) {
        float s = hv[0][r] + hv[1][r] + hv[2][r] + hv[3][r];
        float q = hv[0][r] * hv[0][r] + hv[1][r] * hv[1][r]
                + hv[2][r] * hv[2][r] + hv[3][r] * hv[3][r];
#pragma unroll
        for (int o = 16; o; o >>= 1) {
            s += __shfl_xor_sync(0xffffffffu, s, o);
            q += __shfl_xor_sync(0xffffffffu, q, o);
        }
        float m = s * (1.0f / NINV);
        mu[r] = m;
        rs[r] = rsqrtf(q * (1.0f / NINV) - m * m + 1e-5f);
    }
}

// Apply LN affine and store transposed into the per-warp h buffer ([k][row],
// row stride HSTR floats, 2-way conflict on the STS.128s).
static __device__ __forceinline__ void ln_store(float* shw, int c0, const float hv[4][8],
                                                const float* mu, const float* rs,
                                                float4 g4, float4 b4) {
    float gg[4] = {g4.x, g4.y, g4.z, g4.w};
    float bb[4] = {b4.x, b4.y, b4.z, b4.w};
#pragma unroll
    for (int j = 0; j < 4; j++) {
        float4 lo, hi;
        lo.x = (hv[j][0] - mu[0]) * rs[0] * gg[j] + bb[j];
        lo.y = (hv[j][1] - mu[1]) * rs[1] * gg[j] + bb[j];
        lo.z = (hv[j][2] - mu[2]) * rs[2] * gg[j] + bb[j];
        lo.w = (hv[j][3] - mu[3]) * rs[3] * gg[j] + bb[j];
        hi.x = (hv[j][4] - mu[4]) * rs[4] * gg[j] + bb[j];
        hi.y = (hv[j][5] - mu[5]) * rs[5] * gg[j] + bb[j];
        hi.z = (hv[j][6] - mu[6]) * rs[6] * gg[j] + bb[j];
        hi.w = (hv[j][7] - mu[7]) * rs[7] * gg[j] + bb[j];
        *reinterpret_cast<float4*>(shw + (c0 + j) * HSTR)     = lo;
        *reinterpret_cast<float4*>(shw + (c0 + j) * HSTR + 4) = hi;
    }
}

__global__ void __launch_bounds__(NTHR) evmlp_kernel(
    const float* __restrict__ ten,
    const float* __restrict__ w1, const float* __restrict__ g1, const float* __restrict__ be1,
    const float* __restrict__ w2, const float* __restrict__ b2,
    const float* __restrict__ g2, const float* __restrict__ be2,
    const float* __restrict__ w3, const float* __restrict__ b3,
    float* __restrict__ out)
{
    extern __shared__ __align__(16) float smem[];
    float* s_ten  = smem + OFF_TEN;
    float* s_x1   = smem + OFF_X1;
    float* s_h    = smem + OFF_H;
    float* s_rdiv = s_h;              // phase-A only alias (896 floats)

    const int tid = threadIdx.x;

    // ---------- Phase A: 4 chunks of 8 rows -> x1 (transposed) + x2 out ----------
#pragma unroll 1
    for (int cc = 0; cc < 4; cc++) {
        const long long row0 = (long long)blockIdx.x * RTC + cc * RTW;
        {
            const float4* g4 = reinterpret_cast<const float4*>(ten + row0 * DIMX);
            float4* s4 = reinterpret_cast<float4*>(s_ten);
#pragma unroll
            for (int i = tid; i < (RTW * DIMX) / 4; i += NTHR) s4[i] = g4[i];
        }
        __syncthreads();

        // x10 -> s_x1 [c][rowRTC]
        for (int j = tid; j < RTW * NINV; j += NTHR) {
            int r = j & 7;
            int c = j >> 3;
            s_x1[c * RTC + cc * RTW + r] = s_ten[r * DIMX + c];
        }
        // per-segment sumsq -> x11 + reciprocal divisor
        if (tid < NSEG) {
            int t = tid, base, len;
            if (t < 64)      { base = 3 * t;              len = 3; }
            else if (t < 96) { base = 192 + 5 * (t - 64); len = 5; }
            else             { base = 352 + 7 * (t - 96); len = 7; }
#pragma unroll
            for (int r = 0; r < RTW; r++) {
                const float* e = &s_ten[r * DIMX + NINV + base];
                float ss = 1.0f;
                for (int j = 0; j < len; j++) ss += e[j] * e[j];
                float dv = sqrtf(ss);
                s_x1[(NINV + t) * RTC + cc * RTW + r] = dv - 1.0f;
                s_rdiv[r * NSEG + t] = 1.0f / dv;
            }
        }
        __syncthreads();

        // x2 = eq * rdiv[seg] -> out columns [128, 592)
#pragma unroll 1
        for (int r = 0; r < RTW; r++) {
            float*       orow = out + (row0 + r) * DIMX + NINV;
            const float* erow = &s_ten[r * DIMX + NINV];
            const float* rd   = &s_rdiv[r * NSEG];
            for (unsigned i = tid; i < NEQ; i += NTHR) {
                unsigned s;
                if (i < 192u)      s = i / 3u;
                else if (i < 352u) s = 64u + (i - 192u) / 5u;
                else               s = 96u + (i - 352u) / 7u;
                orow[i] = erow[i] * rd[s];
            }
        }
        __syncthreads();
    }

    // ---------- Phase B: per-warp MLP over its 8 rows ----------
    const int lane = tid & 31;
    const int wrp  = tid >> 5;
    const int c0   = lane * 4;
    const long long rowb = (long long)blockIdx.x * RTC + wrp * RTW;

    float hv[4][8], mu[RTW], rs[RTW];
    float* shw = s_h + wrp * NINV * HSTR;

    // GEMM1: h = x1 @ w1 (K = 240)
    warp_gemm<NCH, RTC>(w1, c0, s_x1 + wrp * RTW, make_float4(0.f, 0.f, 0.f, 0.f), hv);

    // LN1
    ln_warp(hv, mu, rs);
    ln_store(shw, c0, hv, mu, rs,
             __ldg(reinterpret_cast<const float4*>(g1 + c0)),
             __ldg(reinterpret_cast<const float4*>(be1 + c0)));
    __syncwarp();

    // GEMM2: h @ w2 + b2 (K = 128)
    warp_gemm<NINV, HSTR>(w2, c0, shw,
                          __ldg(reinterpret_cast<const float4*>(b2 + c0)), hv);

    // SiLU
#pragma unroll
    for (int j = 0; j < 4; j++)
#pragma unroll
        for (int r = 0; r < RTW; r++) {
            float v = hv[j][r];
            hv[j][r] = v / (1.0f + __expf(-v));
        }

    // LN2
    ln_warp(hv, mu, rs);
    __syncwarp();   // all lanes done reading s_h from GEMM2 before overwrite
    ln_store(shw, c0, hv, mu, rs,
             __ldg(reinterpret_cast<const float4*>(g2 + c0)),
             __ldg(reinterpret_cast<const float4*>(be2 + c0)));
    __syncwarp();

    // GEMM3: h @ w3 + b3 (K = 128) -> out columns [0, 128)
    warp_gemm<NINV, HSTR>(w3, c0, shw,
                          __ldg(reinterpret_cast<const float4*>(b3 + c0)), hv);

#pragma unroll
    for (int r = 0; r < RTW; r++) {
        float4 o;
        o.x = hv[0][r]; o.y = hv[1][r]; o.z = hv[2][r]; o.w = hv[3][r];
        *reinterpret_cast<float4*>(out + (rowb + r) * DIMX + c0) = o;
    }
}

extern "C" void kernel_launch(void* const* d_in, const int* in_sizes, int n_in,
                              void* d_out, int out_size) {
    const float* ten = (const float*)d_in[0];
    // d_in[1] = rep_layout (int64) — compile-time constant layout, unused
    const float* w1  = (const float*)d_in[2];
    const float* g1  = (const float*)d_in[3];
    const float* be1 = (const float*)d_in[4];
    const float* w2  = (const float*)d_in[5];
    const float* b2  = (const float*)d_in[6];
    const float* g2  = (const float*)d_in[7];
    const float* be2 = (const float*)d_in[8];
    const float* w3  = (const float*)d_in[9];
    const float* b3  = (const float*)d_in[10];

    static bool attr_set = false;
    if (!attr_set) {
        cudaFuncSetAttribute(evmlp_kernel,
                             cudaFuncAttributeMaxDynamicSharedMemorySize,
                             SMEM_FLOATS * (int)sizeof(float));
        attr_set = true;
    }
    evmlp_kernel<<<NROWS / RTC, NTHR, SMEM_FLOATS * sizeof(float)>>>(
        ten, w1, g1, be1, w2, b2, g2, be2, w3, b3, (float*)d_out);
}

// round 7
// speedup vs baseline: 1.7790x; 1.4757x over previous
#include <cuda_runtime.h>

#define NROWS 100000
#define DIMX  592
#define NINV  128
#define NEQ   464
#define NCH   240
#define NSEG  112
#define RTW   8        // rows per warp
#define RTC   32       // rows per CTA (4 warps)
#define NTHR  128
#define KT    16       // k-rows per weight tile
#define NBUF  4        // async weight buffers
#define HSTR  12       // h-buffer row stride (floats); row k at 12k, extent 8, max 1532
#define HWARP 1552     // per-warp h buffer floats (12*128 = 1536, pad to 1552)

// ---- shared memory layout (floats) ----
#define OFF_X1 0
#define SZ_X1  (NCH * RTC)            // 7680  : x1, [k][row] stride 32
#define OFF_W  (OFF_X1 + SZ_X1)       // 7680  : 4 weight tile buffers (aliased by s_ten in phase A)
#define SZ_W   (NBUF * KT * NINV)     // 8192
#define OFF_H  (OFF_W + SZ_W)         // 15872 : per-warp h buffers (aliased by s_rdiv in phase A)
#define SZ_H   (4 * HWARP)            // 6208
#define SMEM_FLOATS (OFF_H + SZ_H)    // 22080 floats = 88320 B

// ---- Blackwell packed f32x2 helpers ----
static __device__ __forceinline__ unsigned long long ffma2(unsigned long long a,
                                                           unsigned long long b,
                                                           unsigned long long c) {
    unsigned long long d;
    asm("fma.rn.f32x2 %0, %1, %2, %3;" : "=l"(d) : "l"(a), "l"(b), "l"(c));
    return d;
}
static __device__ __forceinline__ unsigned long long pack2(float x, float y) {
    unsigned long long r;
    asm("mov.b64 %0, {%1, %2};" : "=l"(r)
        : "r"(__float_as_uint(x)), "r"(__float_as_uint(y)));
    return r;
}
static __device__ __forceinline__ void unpack2(unsigned long long v, float& x, float& y) {
    unsigned a, b;
    asm("mov.b64 {%0, %1}, %2;" : "=r"(a), "=r"(b) : "l"(v));
    x = __uint_as_float(a);
    y = __uint_as_float(b);
}

// h-buffer row offset: plain padded stride (proven correct in round 4).
// Row k occupies 8 contiguous floats at 12k (16B aligned); no overlaps.
static __device__ __forceinline__ int hoff(int k) {
    return k * HSTR;
}

// cooperative async copy of one KT x 128 weight tile (8KB, contiguous in gmem)
static __device__ __forceinline__ void copy_tile(float* dst, const float* src, int tid) {
#pragma unroll
    for (int i = 0; i < (KT * NINV) / (4 * NTHR); i++) {   // 4 x 16B per thread
        unsigned d = (unsigned)__cvta_generic_to_shared(dst + (tid + i * NTHR) * 4);
        const float* s = src + (tid + i * NTHR) * 4;
        asm volatile("cp.async.cg.shared.global [%0], [%1], 16;" :: "r"(d), "l"(s));
    }
}
static __device__ __forceinline__ void cp_commit() {
    asm volatile("cp.async.commit_group;");
}
static __device__ __forceinline__ void cp_wait2() {
    asm volatile("cp.async.wait_group 2;");
}

// Staged-weight warp GEMM: 8 rows x 4 channels per thread.
// Weights streamed gmem->smem via cp.async pipeline; x broadcast from shared.
// SWZ=false: x row k at xb + k*RTC (x1 layout). SWZ=true: at xb + hoff(k).
template<int T, bool SWZ>
static __device__ __forceinline__ void gemm_staged(const float* __restrict__ Wg,
                                                   const float* xb, float* s_w,
                                                   int tid, int lane,
                                                   float4 bias, float hv[4][8]) {
    __syncthreads();   // all warps done with s_w from the previous GEMM
    // prologue: prefetch tiles 0..2
#pragma unroll
    for (int p = 0; p < 3; p++) {
        if (p < T) copy_tile(s_w + (p & (NBUF - 1)) * (KT * NINV), Wg + p * KT * NINV, tid);
        cp_commit();
    }
    unsigned long long acc[4][4];
    {
        float bb[4] = {bias.x, bias.y, bias.z, bias.w};
#pragma unroll
        for (int j = 0; j < 4; j++) {
            unsigned long long b = pack2(bb[j], bb[j]);
            acc[j][0] = b; acc[j][1] = b; acc[j][2] = b; acc[j][3] = b;
        }
    }
#pragma unroll 1
    for (int t = 0; t < T; t++) {
        cp_wait2();            // tile t landed (for this thread's copies)
        __syncthreads();       // landed copies visible CTA-wide; buffer (t+3)&3 free
        if (t + 3 < T) copy_tile(s_w + ((t + 3) & (NBUF - 1)) * (KT * NINV),
                                 Wg + (t + 3) * KT * NINV, tid);
        cp_commit();
        const float* wb = s_w + (t & (NBUF - 1)) * (KT * NINV) + lane * 4;
#pragma unroll
        for (int kk = 0; kk < KT; kk++) {
            int k = t * KT + kk;
            float4 wv = *reinterpret_cast<const float4*>(wb + kk * NINV);
            const float* xp = SWZ ? (xb + hoff(k)) : (xb + k * RTC);
            ulonglong2 xa = *reinterpret_cast<const ulonglong2*>(xp);
            ulonglong2 xc = *reinterpret_cast<const ulonglong2*>(xp + 4);
            unsigned long long wp0 = pack2(wv.x, wv.x);
            unsigned long long wp1 = pack2(wv.y, wv.y);
            unsigned long long wp2 = pack2(wv.z, wv.z);
            unsigned long long wp3 = pack2(wv.w, wv.w);
            acc[0][0] = ffma2(xa.x, wp0, acc[0][0]);
            acc[0][1] = ffma2(xa.y, wp0, acc[0][1]);
            acc[0][2] = ffma2(xc.x, wp0, acc[0][2]);
            acc[0][3] = ffma2(xc.y, wp0, acc[0][3]);
            acc[1][0] = ffma2(xa.x, wp1, acc[1][0]);
            acc[1][1] = ffma2(xa.y, wp1, acc[1][1]);
            acc[1][2] = ffma2(xc.x, wp1, acc[1][2]);
            acc[1][3] = ffma2(xc.y, wp1, acc[1][3]);
            acc[2][0] = ffma2(xa.x, wp2, acc[2][0]);
            acc[2][1] = ffma2(xa.y, wp2, acc[2][1]);
            acc[2][2] = ffma2(xc.x, wp2, acc[2][2]);
            acc[2][3] = ffma2(xc.y, wp2, acc[2][3]);
            acc[3][0] = ffma2(xa.x, wp3, acc[3][0]);
            acc[3][1] = ffma2(xa.y, wp3, acc[3][1]);
            acc[3][2] = ffma2(xc.x, wp3, acc[3][2]);
            acc[3][3] = ffma2(xc.y, wp3, acc[3][3]);
        }
    }
#pragma unroll
    for (int j = 0; j < 4; j++) {
        unpack2(acc[j][0], hv[j][0], hv[j][1]);
        unpack2(acc[j][1], hv[j][2], hv[j][3]);
        unpack2(acc[j][2], hv[j][4], hv[j][5]);
        unpack2(acc[j][3], hv[j][6], hv[j][7]);
    }
}

// Warp-local LayerNorm stats (128 channels across warp, 8 rows per thread set)
static __device__ __forceinline__ void ln_warp(const float hv[4][8], float* mu, float* rs) {
#pragma unroll
    for (int r = 0; r < RTW; r++) {
        float s = hv[0][r] + hv[1][r] + hv[2][r] + hv[3][r];
        float q = hv[0][r] * hv[0][r] + hv[1][r] * hv[1][r]
                + hv[2][r] * hv[2][r] + hv[3][r] * hv[3][r];
#pragma unroll
        for (int o = 16; o; o >>= 1) {
            s += __shfl_xor_sync(0xffffffffu, s, o);
            q += __shfl_xor_sync(0xffffffffu, q, o);
        }
        float m = s * (1.0f / NINV);
        mu[r] = m;
        rs[r] = rsqrtf(q * (1.0f / NINV) - m * m + 1e-5f);
    }
}

// LN affine + transposed store into per-warp h buffer
static __device__ __forceinline__ void ln_store(float* shw, int c0, const float hv[4][8],
                                                const float* mu, const float* rs,
                                                float4 g4, float4 b4) {
    float gg[4] = {g4.x, g4.y, g4.z, g4.w};
    float bb[4] = {b4.x, b4.y, b4.z, b4.w};
#pragma unroll
    for (int j = 0; j < 4; j++) {
        float4 lo, hi;
        lo.x = (hv[j][0] - mu[0]) * rs[0] * gg[j] + bb[j];
        lo.y = (hv[j][1] - mu[1]) * rs[1] * gg[j] + bb[j];
        lo.z = (hv[j][2] - mu[2]) * rs[2] * gg[j] + bb[j];
        lo.w = (hv[j][3] - mu[3]) * rs[3] * gg[j] + bb[j];
        hi.x = (hv[j][4] - mu[4]) * rs[4] * gg[j] + bb[j];
        hi.y = (hv[j][5] - mu[5]) * rs[5] * gg[j] + bb[j];
        hi.z = (hv[j][6] - mu[6]) * rs[6] * gg[j] + bb[j];
        hi.w = (hv[j][7] - mu[7]) * rs[7] * gg[j] + bb[j];
        float* p = shw + hoff(c0 + j);
        *reinterpret_cast<float4*>(p)     = lo;
        *reinterpret_cast<float4*>(p + 4) = hi;
    }
}

__global__ void __launch_bounds__(NTHR) evmlp_kernel(
    const float* __restrict__ ten,
    const float* __restrict__ w1, const float* __restrict__ g1, const float* __restrict__ be1,
    const float* __restrict__ w2, const float* __restrict__ b2,
    const float* __restrict__ g2, const float* __restrict__ be2,
    const float* __restrict__ w3, const float* __restrict__ b3,
    float* __restrict__ out)
{
    extern __shared__ __align__(16) float smem[];
    float* s_x1   = smem + OFF_X1;
    float* s_w    = smem + OFF_W;
    float* s_h    = smem + OFF_H;
    float* s_ten  = s_w;              // phase-A alias (4736 <= 8192 floats)
    float* s_rdiv = s_h;              // phase-A alias (896  <= 6208 floats)

    const int tid = threadIdx.x;

    // ---------- Phase A: 4 chunks of 8 rows -> x1 (transposed) + x2 out ----------
#pragma unroll 1
    for (int cc = 0; cc < 4; cc++) {
        const long long row0 = (long long)blockIdx.x * RTC + cc * RTW;
        {
            const float4* g4 = reinterpret_cast<const float4*>(ten + row0 * DIMX);
            float4* s4 = reinterpret_cast<float4*>(s_ten);
#pragma unroll
            for (int i = tid; i < (RTW * DIMX) / 4; i += NTHR) s4[i] = g4[i];
        }
        __syncthreads();

        // x10 -> s_x1 [c][row32]
        for (int j = tid; j < RTW * NINV; j += NTHR) {
            int r = j & 7;
            int c = j >> 3;
            s_x1[c * RTC + cc * RTW + r] = s_ten[r * DIMX + c];
        }
        // per-segment sumsq -> x11 + reciprocal divisor
        if (tid < NSEG) {
            int t = tid, base, len;
            if (t < 64)      { base = 3 * t;              len = 3; }
            else if (t < 96) { base = 192 + 5 * (t - 64); len = 5; }
            else             { base = 352 + 7 * (t - 96); len = 7; }
#pragma unroll
            for (int r = 0; r < RTW; r++) {
                const float* e = &s_ten[r * DIMX + NINV + base];
                float ss = 1.0f;
                for (int j = 0; j < len; j++) ss += e[j] * e[j];
                float dv = sqrtf(ss);
                s_x1[(NINV + t) * RTC + cc * RTW + r] = dv - 1.0f;
                s_rdiv[r * NSEG + t] = 1.0f / dv;
            }
        }
        __syncthreads();

        // x2 = eq * rdiv[seg] -> out columns [128, 592)
#pragma unroll 1
        for (int r = 0; r < RTW; r++) {
            float*       orow = out + (row0 + r) * DIMX + NINV;
            const float* erow = &s_ten[r * DIMX + NINV];
            const float* rd   = &s_rdiv[r * NSEG];
            for (unsigned i = tid; i < NEQ; i += NTHR) {
                unsigned s;
                if (i < 192u)      s = i / 3u;
                else if (i < 352u) s = 64u + (i - 192u) / 5u;
                else               s = 96u + (i - 352u) / 7u;
                orow[i] = erow[i] * rd[s];
            }
        }
        __syncthreads();   // s_ten / s_rdiv free after this (aliased below)
    }

    // ---------- Phase B: per-warp MLP over its 8 rows ----------
    const int lane = tid & 31;
    const int wrp  = tid >> 5;
    const int c0   = lane * 4;
    const long long rowb = (long long)blockIdx.x * RTC + wrp * RTW;

    float hv[4][8], mu[RTW], rs[RTW];
    float* shw = s_h + wrp * HWARP;

    // GEMM1: h = x1 @ w1 (K = 240, 15 tiles)
    gemm_staged<NCH / KT, false>(w1, s_x1 + wrp * RTW, s_w, tid, lane,
                                 make_float4(0.f, 0.f, 0.f, 0.f), hv);

    // LN1
    ln_warp(hv, mu, rs);
    ln_store(shw, c0, hv, mu, rs,
             __ldg(reinterpret_cast<const float4*>(g1 + c0)),
             __ldg(reinterpret_cast<const float4*>(be1 + c0)));
    __syncwarp();

    // GEMM2: h @ w2 + b2 (K = 128, 8 tiles)
    gemm_staged<NINV / KT, true>(w2, shw, s_w, tid, lane,
                                 __ldg(reinterpret_cast<const float4*>(b2 + c0)), hv);

    // SiLU
#pragma unroll
    for (int j = 0; j < 4; j++)
#pragma unroll
        for (int r = 0; r < RTW; r++) {
            float v = hv[j][r];
            hv[j][r] = v / (1.0f + __expf(-v));
        }

    // LN2
    ln_warp(hv, mu, rs);
    __syncwarp();   // all lanes done reading s_h from GEMM2 before overwrite
    ln_store(shw, c0, hv, mu, rs,
             __ldg(reinterpret_cast<const float4*>(g2 + c0)),
             __ldg(reinterpret_cast<const float4*>(be2 + c0)));
    __syncwarp();

    // GEMM3: h @ w3 + b3 (K = 128, 8 tiles) -> out columns [0, 128)
    gemm_staged<NINV / KT, true>(w3, shw, s_w, tid, lane,
                                 __ldg(reinterpret_cast<const float4*>(b3 + c0)), hv);

#pragma unroll
    for (int r = 0; r < RTW; r++) {
        float4 o;
        o.x = hv[0][r]; o.y = hv[1][r]; o.z = hv[2][r]; o.w = hv[3][r];
        *reinterpret_cast<float4*>(out + (rowb + r) * DIMX + c0) = o;
    }
}

extern "C" void kernel_launch(void* const* d_in, const int* in_sizes, int n_in,
                              void* d_out, int out_size) {
    const float* ten = (const float*)d_in[0];
    // d_in[1] = rep_layout (int64) — compile-time constant layout, unused
    const float* w1  = (const float*)d_in[2];
    const float* g1  = (const float*)d_in[3];
    const float* be1 = (const float*)d_in[4];
    const float* w2  = (const float*)d_in[5];
    const float* b2  = (const float*)d_in[6];
    const float* g2  = (const float*)d_in[7];
    const float* be2 = (const float*)d_in[8];
    const float* w3  = (const float*)d_in[9];
    const float* b3  = (const float*)d_in[10];

    static bool attr_set = false;
    if (!attr_set) {
        cudaFuncSetAttribute(evmlp_kernel,
                             cudaFuncAttributeMaxDynamicSharedMemorySize,
                             SMEM_FLOATS * (int)sizeof(float));
        attr_set = true;
    }
    evmlp_kernel<<<NROWS / RTC, NTHR, SMEM_FLOATS * sizeof(float)>>>(
        ten, w1, g1, be1, w2, b2, g2, be2, w3, b3, (float*)d_out);
}

// round 8
// speedup vs baseline: 2.3687x; 1.3314x over previous
#include <cuda_runtime.h>

#define NROWS 100000
#define DIMX  592
#define NINV  128
#define NEQ   464
#define NCH   240
#define NSEG  112
#define RTW   8        // rows per warp
#define RTC   32       // rows per CTA (4 warps)
#define NTHR  128
#define KT    16       // k-rows per weight tile
#define NBUF  3        // async weight buffers (prefetch distance 2)
#define HSTR  12       // h-buffer row stride (floats); row k at 12k, extent 8, max 1532
#define HWARP 1552     // per-warp h buffer floats

// ---- shared memory layout (floats) ----
// Region W: weight tile ring (phase A: aliased by s_ten + s_rdiv)
// Region X: x1 during GEMM1, then per-warp h buffers (x1 dead after GEMM1)
#define OFF_W  0
#define SZ_W   (NBUF * KT * NINV)     // 6144 floats (24 KB)
#define OFF_X  SZ_W
#define SZ_X   (NCH * RTC)            // 7680 floats (30 KB) >= 4*HWARP = 6208
#define SMEM_FLOATS (OFF_X + SZ_X)    // 13824 floats = 55296 B -> 4 CTAs/SM

// ---- Blackwell packed f32x2 helpers ----
static __device__ __forceinline__ unsigned long long ffma2(unsigned long long a,
                                                           unsigned long long b,
                                                           unsigned long long c) {
    unsigned long long d;
    asm("fma.rn.f32x2 %0, %1, %2, %3;" : "=l"(d) : "l"(a), "l"(b), "l"(c));
    return d;
}
static __device__ __forceinline__ unsigned long long pack2(float x, float y) {
    unsigned long long r;
    asm("mov.b64 %0, {%1, %2};" : "=l"(r)
        : "r"(__float_as_uint(x)), "r"(__float_as_uint(y)));
    return r;
}
static __device__ __forceinline__ void unpack2(unsigned long long v, float& x, float& y) {
    unsigned a, b;
    asm("mov.b64 {%0, %1}, %2;" : "=r"(a), "=r"(b) : "l"(v));
    x = __uint_as_float(a);
    y = __uint_as_float(b);
}

// h-buffer row offset: padded stride 12 (proven correct). Row k: 8 contiguous
// floats at 12k, 16B aligned, max 1532 < HWARP.
static __device__ __forceinline__ int hoff(int k) {
    return k * HSTR;
}

// cooperative async copy of one KT x 128 weight tile (8KB, contiguous in gmem)
static __device__ __forceinline__ void copy_tile(float* dst, const float* src, int tid) {
#pragma unroll
    for (int i = 0; i < (KT * NINV) / (4 * NTHR); i++) {   // 4 x 16B per thread
        unsigned d = (unsigned)__cvta_generic_to_shared(dst + (tid + i * NTHR) * 4);
        const float* s = src + (tid + i * NTHR) * 4;
        asm volatile("cp.async.cg.shared.global [%0], [%1], 16;" :: "r"(d), "l"(s));
    }
}
static __device__ __forceinline__ void cp_commit() {
    asm volatile("cp.async.commit_group;");
}
static __device__ __forceinline__ void cp_wait1() {
    asm volatile("cp.async.wait_group 1;");
}

// Staged-weight warp GEMM: 8 rows x 4 channels per thread.
// Weights streamed gmem->smem via 3-deep cp.async ring; x broadcast from shared.
// SWZ=false: x row k at xb + k*RTC (x1 layout). SWZ=true: at xb + hoff(k).
template<int T, bool SWZ>
static __device__ __forceinline__ void gemm_staged(const float* __restrict__ Wg,
                                                   const float* xb, float* s_w,
                                                   int tid, int lane,
                                                   float4 bias, float hv[4][8]) {
    __syncthreads();   // all warps done with s_w from the previous GEMM
    // prologue: prefetch tiles 0..1
#pragma unroll
    for (int p = 0; p < 2; p++) {
        copy_tile(s_w + p * (KT * NINV), Wg + p * KT * NINV, tid);
        cp_commit();
    }
    unsigned long long acc[4][4];
    {
        float bb[4] = {bias.x, bias.y, bias.z, bias.w};
#pragma unroll
        for (int j = 0; j < 4; j++) {
            unsigned long long b = pack2(bb[j], bb[j]);
            acc[j][0] = b; acc[j][1] = b; acc[j][2] = b; acc[j][3] = b;
        }
    }
    int buf = 0, pbuf = 2;
#pragma unroll 1
    for (int t = 0; t < T; t++) {
        cp_wait1();            // tile t landed (<=1 group outstanding)
        __syncthreads();       // visible CTA-wide; buffer pbuf fully consumed
        if (t + 2 < T) copy_tile(s_w + pbuf * (KT * NINV),
                                 Wg + (t + 2) * KT * NINV, tid);
        cp_commit();
        const float* wb = s_w + buf * (KT * NINV) + lane * 4;
        if (++buf == NBUF) buf = 0;
        if (++pbuf == NBUF) pbuf = 0;
#pragma unroll
        for (int kk = 0; kk < KT; kk++) {
            int k = t * KT + kk;
            float4 wv = *reinterpret_cast<const float4*>(wb + kk * NINV);
            const float* xp = SWZ ? (xb + hoff(k)) : (xb + k * RTC);
            ulonglong2 xa = *reinterpret_cast<const ulonglong2*>(xp);
            ulonglong2 xc = *reinterpret_cast<const ulonglong2*>(xp + 4);
            unsigned long long wp0 = pack2(wv.x, wv.x);
            unsigned long long wp1 = pack2(wv.y, wv.y);
            unsigned long long wp2 = pack2(wv.z, wv.z);
            unsigned long long wp3 = pack2(wv.w, wv.w);
            acc[0][0] = ffma2(xa.x, wp0, acc[0][0]);
            acc[0][1] = ffma2(xa.y, wp0, acc[0][1]);
            acc[0][2] = ffma2(xc.x, wp0, acc[0][2]);
            acc[0][3] = ffma2(xc.y, wp0, acc[0][3]);
            acc[1][0] = ffma2(xa.x, wp1, acc[1][0]);
            acc[1][1] = ffma2(xa.y, wp1, acc[1][1]);
            acc[1][2] = ffma2(xc.x, wp1, acc[1][2]);
            acc[1][3] = ffma2(xc.y, wp1, acc[1][3]);
            acc[2][0] = ffma2(xa.x, wp2, acc[2][0]);
            acc[2][1] = ffma2(xa.y, wp2, acc[2][1]);
            acc[2][2] = ffma2(xc.x, wp2, acc[2][2]);
            acc[2][3] = ffma2(xc.y, wp2, acc[2][3]);
            acc[3][0] = ffma2(xa.x, wp3, acc[3][0]);
            acc[3][1] = ffma2(xa.y, wp3, acc[3][1]);
            acc[3][2] = ffma2(xc.x, wp3, acc[3][2]);
            acc[3][3] = ffma2(xc.y, wp3, acc[3][3]);
        }
    }
#pragma unroll
    for (int j = 0; j < 4; j++) {
        unpack2(acc[j][0], hv[j][0], hv[j][1]);
        unpack2(acc[j][1], hv[j][2], hv[j][3]);
        unpack2(acc[j][2], hv[j][4], hv[j][5]);
        unpack2(acc[j][3], hv[j][6], hv[j][7]);
    }
}

// Warp-local LayerNorm stats (128 channels across warp, 8 rows per thread set)
static __device__ __forceinline__ void ln_warp(const float hv[4][8], float* mu, float* rs) {
#pragma unroll
    for (int r = 0; r < RTW; r++) {
        float s = hv[0][r] + hv[1][r] + hv[2][r] + hv[3][r];
        float q = hv[0][r] * hv[0][r] + hv[1][r] * hv[1][r]
                + hv[2][r] * hv[2][r] + hv[3][r] * hv[3][r];
#pragma unroll
        for (int o = 16; o; o >>= 1) {
            s += __shfl_xor_sync(0xffffffffu, s, o);
            q += __shfl_xor_sync(0xffffffffu, q, o);
        }
        float m = s * (1.0f / NINV);
        mu[r] = m;
        rs[r] = rsqrtf(q * (1.0f / NINV) - m * m + 1e-5f);
    }
}

// LN affine + transposed store into per-warp h buffer
static __device__ __forceinline__ void ln_store(float* shw, int c0, const float hv[4][8],
                                                const float* mu, const float* rs,
                                                float4 g4, float4 b4) {
    float gg[4] = {g4.x, g4.y, g4.z, g4.w};
    float bb[4] = {b4.x, b4.y, b4.z, b4.w};
#pragma unroll
    for (int j = 0; j < 4; j++) {
        float4 lo, hi;
        lo.x = (hv[j][0] - mu[0]) * rs[0] * gg[j] + bb[j];
        lo.y = (hv[j][1] - mu[1]) * rs[1] * gg[j] + bb[j];
        lo.z = (hv[j][2] - mu[2]) * rs[2] * gg[j] + bb[j];
        lo.w = (hv[j][3] - mu[3]) * rs[3] * gg[j] + bb[j];
        hi.x = (hv[j][4] - mu[4]) * rs[4] * gg[j] + bb[j];
        hi.y = (hv[j][5] - mu[5]) * rs[5] * gg[j] + bb[j];
        hi.z = (hv[j][6] - mu[6]) * rs[6] * gg[j] + bb[j];
        hi.w = (hv[j][7] - mu[7]) * rs[7] * gg[j] + bb[j];
        float* p = shw + hoff(c0 + j);
        *reinterpret_cast<float4*>(p)     = lo;
        *reinterpret_cast<float4*>(p + 4) = hi;
    }
}

__global__ void __launch_bounds__(NTHR) evmlp_kernel(
    const float* __restrict__ ten,
    const float* __restrict__ w1, const float* __restrict__ g1, const float* __restrict__ be1,
    const float* __restrict__ w2, const float* __restrict__ b2,
    const float* __restrict__ g2, const float* __restrict__ be2,
    const float* __restrict__ w3, const float* __restrict__ b3,
    float* __restrict__ out)
{
    extern __shared__ __align__(16) float smem[];
    float* s_w    = smem + OFF_W;
    float* s_x1   = smem + OFF_X;
    float* s_h    = smem + OFF_X;               // alias: x1 dead after GEMM1
    float* s_ten  = s_w;                        // phase-A alias (4736 <= 6144)
    float* s_rdiv = s_w + RTW * DIMX;           // phase-A alias (4736+896 <= 6144)

    const int tid = threadIdx.x;

    // ---------- Phase A: 4 chunks of 8 rows -> x1 (transposed) + x2 out ----------
#pragma unroll 1
    for (int cc = 0; cc < 4; cc++) {
        const long long row0 = (long long)blockIdx.x * RTC + cc * RTW;
        {
            const float4* g4 = reinterpret_cast<const float4*>(ten + row0 * DIMX);
            float4* s4 = reinterpret_cast<float4*>(s_ten);
#pragma unroll
            for (int i = tid; i < (RTW * DIMX) / 4; i += NTHR) s4[i] = g4[i];
        }
        __syncthreads();

        // x10 -> s_x1 [c][row32]
        for (int j = tid; j < RTW * NINV; j += NTHR) {
            int r = j & 7;
            int c = j >> 3;
            s_x1[c * RTC + cc * RTW + r] = s_ten[r * DIMX + c];
        }
        // per-segment sumsq -> x11 + reciprocal divisor
        if (tid < NSEG) {
            int t = tid, base, len;
            if (t < 64)      { base = 3 * t;              len = 3; }
            else if (t < 96) { base = 192 + 5 * (t - 64); len = 5; }
            else             { base = 352 + 7 * (t - 96); len = 7; }
#pragma unroll
            for (int r = 0; r < RTW; r++) {
                const float* e = &s_ten[r * DIMX + NINV + base];
                float ss = 1.0f;
                for (int j = 0; j < len; j++) ss += e[j] * e[j];
                float dv = sqrtf(ss);
                s_x1[(NINV + t) * RTC + cc * RTW + r] = dv - 1.0f;
                s_rdiv[r * NSEG + t] = 1.0f / dv;
            }
        }
        __syncthreads();

        // x2 = eq * rdiv[seg] -> out columns [128, 592)
#pragma unroll 1
        for (int r = 0; r < RTW; r++) {
            float*       orow = out + (row0 + r) * DIMX + NINV;
            const float* erow = &s_ten[r * DIMX + NINV];
            const float* rd   = &s_rdiv[r * NSEG];
            for (unsigned i = tid; i < NEQ; i += NTHR) {
                unsigned s;
                if (i < 192u)      s = i / 3u;
                else if (i < 352u) s = 64u + (i - 192u) / 5u;
                else               s = 96u + (i - 352u) / 7u;
                orow[i] = erow[i] * rd[s];
            }
        }
        __syncthreads();   // s_ten / s_rdiv (weight region) free after this
    }

    // ---------- Phase B: per-warp MLP over its 8 rows ----------
    const int lane = tid & 31;
    const int wrp  = tid >> 5;
    const int c0   = lane * 4;
    const long long rowb = (long long)blockIdx.x * RTC + wrp * RTW;

    float hv[4][8], mu[RTW], rs[RTW];
    float* shw = s_h + wrp * HWARP;

    // GEMM1: h = x1 @ w1 (K = 240, 15 tiles)
    gemm_staged<NCH / KT, false>(w1, s_x1 + wrp * RTW, s_w, tid, lane,
                                 make_float4(0.f, 0.f, 0.f, 0.f), hv);

    // LN1 (barrier: all warps done reading x1 before h overwrites it)
    ln_warp(hv, mu, rs);
    __syncthreads();
    ln_store(shw, c0, hv, mu, rs,
             __ldg(reinterpret_cast<const float4*>(g1 + c0)),
             __ldg(reinterpret_cast<const float4*>(be1 + c0)));
    __syncwarp();

    // GEMM2: h @ w2 + b2 (K = 128, 8 tiles)
    gemm_staged<NINV / KT, true>(w2, shw, s_w, tid, lane,
                                 __ldg(reinterpret_cast<const float4*>(b2 + c0)), hv);

    // SiLU
#pragma unroll
    for (int j = 0; j < 4; j++)
#pragma unroll
        for (int r = 0; r < RTW; r++) {
            float v = hv[j][r];
            hv[j][r] = v / (1.0f + __expf(-v));
        }

    // LN2
    ln_warp(hv, mu, rs);
    __syncwarp();   // all lanes done reading s_h from GEMM2 before overwrite
    ln_store(shw, c0, hv, mu, rs,
             __ldg(reinterpret_cast<const float4*>(g2 + c0)),
             __ldg(reinterpret_cast<const float4*>(be2 + c0)));
    __syncwarp();

    // GEMM3: h @ w3 + b3 (K = 128, 8 tiles) -> out columns [0, 128)
    gemm_staged<NINV / KT, true>(w3, shw, s_w, tid, lane,
                                 __ldg(reinterpret_cast<const float4*>(b3 + c0)), hv);

#pragma unroll
    for (int r = 0; r < RTW; r++) {
        float4 o;
        o.x = hv[0][r]; o.y = hv[1][r]; o.z = hv[2][r]; o.w = hv[3][r];
        *reinterpret_cast<float4*>(out + (rowb + r) * DIMX + c0) = o;
    }
}

extern "C" void kernel_launch(void* const* d_in, const int* in_sizes, int n_in,
                              void* d_out, int out_size) {
    const float* ten = (const float*)d_in[0];
    // d_in[1] = rep_layout (int64) — compile-time constant layout, unused
    const float* w1  = (const float*)d_in[2];
    const float* g1  = (const float*)d_in[3];
    const float* be1 = (const float*)d_in[4];
    const float* w2  = (const float*)d_in[5];
    const float* b2  = (const float*)d_in[6];
    const float* g2  = (const float*)d_in[7];
    const float* be2 = (const float*)d_in[8];
    const float* w3  = (const float*)d_in[9];
    const float* b3  = (const float*)d_in[10];

    static bool attr_set = false;
    if (!attr_set) {
        cudaFuncSetAttribute(evmlp_kernel,
                             cudaFuncAttributeMaxDynamicSharedMemorySize,
                             SMEM_FLOATS * (int)sizeof(float));
        attr_set = true;
    }
    evmlp_kernel<<<NROWS / RTC, NTHR, SMEM_FLOATS * sizeof(float)>>>(
        ten, w1, g1, be1, w2, b2, g2, be2, w3, b3, (float*)d_out);
}